// round 3
// baseline (speedup 1.0000x reference)
#include <cuda_runtime.h>
#include <math.h>

#define NB 32
#define NT 256
#define NWARP 8

// ---------------- scratch (device globals) ------------------------------------
__device__ __align__(16) float g_h0[256];
__device__ __align__(16) float g_attlog[32];
__device__ __align__(16) float g_gh[768];
__device__ __align__(16) float g_comb[256];
__device__ __align__(16) float g_hnew[256];
__device__ unsigned g_barcnt = 0;
__device__ unsigned g_bargen = 0;

// ---------------- scoped atomics ----------------------------------------------
__device__ __forceinline__ unsigned ld_acq(unsigned* p) {
    unsigned v;
    asm volatile("ld.acquire.gpu.global.u32 %0,[%1];" : "=r"(v) : "l"(p) : "memory");
    return v;
}
__device__ __forceinline__ unsigned atom_add_rel(unsigned* p, unsigned v) {
    unsigned o;
    asm volatile("atom.add.release.gpu.global.u32 %0,[%1],%2;" : "=r"(o) : "l"(p), "r"(v) : "memory");
    return o;
}
__device__ __forceinline__ void st_rlx(unsigned* p, unsigned v) {
    asm volatile("st.relaxed.gpu.global.u32 [%0],%1;" :: "l"(p), "r"(v) : "memory");
}

// CG-style grid barrier: bar.sync + tid0 release-arrive / acquire-spin.
// Graph-replay safe: g_barcnt returns to 0; g_bargen compared wrap-safely
// against a generation base read before the first arrival.
__device__ __forceinline__ void gsync(unsigned target, bool wait) {
    __syncthreads();
    if (threadIdx.x == 0) {
        if (atom_add_rel(&g_barcnt, 1u) == NB - 1) {
            st_rlx(&g_barcnt, 0u);
            atom_add_rel(&g_bargen, 1u);
        } else if (wait) {
            while ((int)(ld_acq(&g_bargen) - target) < 0) { }
        }
    }
    __syncthreads();
}

// ---------------- helpers ------------------------------------------------------
__device__ __forceinline__ float warp_sum(float v) {
#pragma unroll
    for (int o = 16; o; o >>= 1) v += __shfl_xor_sync(0xffffffffu, v, o);
    return v;
}
__device__ __forceinline__ float warp_max(float v) {
#pragma unroll
    for (int o = 16; o; o >>= 1) v = fmaxf(v, __shfl_xor_sync(0xffffffffu, v, o));
    return v;
}
__device__ __forceinline__ float dot4(float4 a, float4 b) {
    return a.x * b.x + a.y * b.y + a.z * b.z + a.w * b.w;
}

// ---------------- fused decoder step -------------------------------------------
__global__ void __launch_bounds__(NT, 1)
attn_decoder_fused(const int* __restrict__ inp,
                   const float* __restrict__ hidden,   // [256]
                   const float* __restrict__ enc,      // [20,256]
                   const int* __restrict__ cond,       // [2]
                   const int* __restrict__ is_head,    // [1]
                   const float* __restrict__ emb,      // [29,256]
                   const float* __restrict__ w_l2d,    // [256,264]
                   const float* __restrict__ b_l2d,
                   const float* __restrict__ w_attn,   // [20,512]
                   const float* __restrict__ b_attn,
                   const float* __restrict__ w_comb,   // [256,512]
                   const float* __restrict__ b_comb,
                   const float* __restrict__ w_ih,     // [768,256]
                   const float* __restrict__ w_hh,     // [768,256]
                   const float* __restrict__ b_ih,
                   const float* __restrict__ b_hh,
                   const float* __restrict__ w_out,    // [29,256]
                   const float* __restrict__ b_out,
                   float* __restrict__ out)            // [305]
{
    const int tid  = threadIdx.x;
    const int lane = tid & 31;
    const int wrp  = tid >> 5;
    const int gw   = blockIdx.x * NWARP + wrp;       // 0..255

    unsigned gen0 = 0;
    if (tid == 0) gen0 = ld_acq(&g_bargen);          // stable: no bump before all arrive

    const int head = __ldg(is_head);
    const float* erow = emb + __ldg(inp) * 256;

    // embedded slices for this lane
    float4 e0 = __ldg((const float4*)erow + lane);
    float4 e1 = __ldg((const float4*)erow + 32 + lane);

    // ---- P1: h0 row gw (head path) + emb-half partials (kept per-lane) ------
    float h0v = 0.f;                                  // broadcast in all lanes
    if (head) {
        const float* wr = w_l2d + gw * 264;
        float4 w0 = __ldg((const float4*)wr + lane);
        float4 w1 = __ldg((const float4*)(wr + 128) + lane);
        float4 x0 = __ldg((const float4*)hidden + lane);
        float4 x1 = __ldg((const float4*)hidden + 32 + lane);
        float s = dot4(w0, x0) + dot4(w1, x1);
        int c0 = __ldg(cond), c1 = __ldg(cond + 1);
        if (lane < 8) {
            float xv = (lane == c0 || lane == 4 + c1) ? 1.f : 0.f;
            s += wr[256 + lane] * xv;
        }
        h0v = warp_sum(s) + __ldg(b_l2d + gw);
        if (lane == 0) __stcg(g_h0 + gw, h0v);
    }
    const float* wc = w_comb + gw * 512;
    float ce_p = dot4(__ldg((const float4*)wc + lane), e0) +
                 dot4(__ldg((const float4*)wc + 32 + lane), e1);   // per-lane partial
    float ae_p = 0.f;
    if (gw < 20) {
        const float* wa = w_attn + gw * 512;
        ae_p = dot4(__ldg((const float4*)wa + lane), e0) +
               dot4(__ldg((const float4*)wa + 32 + lane), e1);
    }

    // prefetch P2 weights (addresses barrier-independent)
    float4 wh[3][2];
    float  bh[3];
#pragma unroll
    for (int r = 0; r < 3; r++) {
        const float* w = w_hh + (gw * 3 + r) * 256;
        wh[r][0] = __ldg((const float4*)w + lane);
        wh[r][1] = __ldg((const float4*)w + 32 + lane);
        bh[r] = __ldg(b_hh + gw * 3 + r);
    }
    float4 wa1_0, wa1_1; float ba = 0.f;
    if (gw < 20) {
        const float* wa = w_attn + gw * 512 + 256;
        wa1_0 = __ldg((const float4*)wa + lane);
        wa1_1 = __ldg((const float4*)wa + 32 + lane);
        ba = __ldg(b_attn + gw);
    }
    gsync(gen0 + 1, true);                                          // ---- gb1

    // ---- P2: gh rows (3/warp) + attention logit (h0 half) -------------------
    float4 x0, x1;
    if (head) {
        x0 = __ldcg((const float4*)g_h0 + lane);
        x1 = __ldcg((const float4*)g_h0 + 32 + lane);
    } else {
        x0 = __ldg((const float4*)hidden + lane);
        x1 = __ldg((const float4*)hidden + 32 + lane);
    }
#pragma unroll
    for (int r = 0; r < 3; r++) {
        float s = warp_sum(dot4(wh[r][0], x0) + dot4(wh[r][1], x1));
        if (lane == 0) __stcg(g_gh + gw * 3 + r, s + bh[r]);
    }
    if (gw < 20) {
        float s = warp_sum(ae_p + dot4(wa1_0, x0) + dot4(wa1_1, x1));
        if (lane == 0) __stcg(g_attlog + gw, s + ba);
    }

    // prefetch P3 weights
    float4 wch0 = __ldg((const float4*)(wc + 256) + lane);
    float4 wch1 = __ldg((const float4*)(wc + 256) + 32 + lane);
    float  bc   = __ldg(b_comb + gw);
    gsync(gen0 + 2, true);                                          // ---- gb2

    // ---- P3: per-warp softmax + attn_applied slices + comb row --------------
    {
        float v = (lane < 20) ? __ldcg(g_attlog + lane) : -1e30f;
        float m = warp_max(v);
        float ex = (lane < 20) ? expf(v - m) : 0.f;
        float sum = warp_sum(ex);
        float w = ex / sum;
        if (gw == 0 && lane < 20) out[285 + lane] = w;
        float4 a0 = {0.f, 0.f, 0.f, 0.f}, a1 = {0.f, 0.f, 0.f, 0.f};
#pragma unroll
        for (int l = 0; l < 20; l++) {
            float wl = __shfl_sync(0xffffffffu, w, l);
            float4 q0 = __ldg((const float4*)(enc + l * 256) + lane);
            float4 q1 = __ldg((const float4*)(enc + l * 256) + 32 + lane);
            a0.x += wl * q0.x; a0.y += wl * q0.y; a0.z += wl * q0.z; a0.w += wl * q0.w;
            a1.x += wl * q1.x; a1.y += wl * q1.y; a1.z += wl * q1.z; a1.w += wl * q1.w;
        }
        float sc = warp_sum(ce_p + dot4(wch0, a0) + dot4(wch1, a1));
        if (lane == 0) __stcg(g_comb + gw, fmaxf(sc + bc, 0.f));
    }

    // prefetch P4: w_ih rows, gh values (final after gb2), biases, h0 element
    float4 wi[3][2];
#pragma unroll
    for (int r = 0; r < 3; r++) {
        const float* w = w_ih + (r * 256 + gw) * 256;
        wi[r][0] = __ldg((const float4*)w + lane);
        wi[r][1] = __ldg((const float4*)w + 32 + lane);
    }
    float ghr = __ldcg(g_gh + gw);
    float ghz = __ldcg(g_gh + 256 + gw);
    float ghn = __ldcg(g_gh + 512 + gw);
    float bir = __ldg(b_ih + gw), biz = __ldg(b_ih + 256 + gw), bin = __ldg(b_ih + 512 + gw);
    float h0o = head ? h0v : __ldg(hidden + gw);
    gsync(gen0 + 3, true);                                          // ---- gb3

    // ---- P4: gi rows + fused GRU for element gw -----------------------------
    {
        float4 c0 = __ldcg((const float4*)g_comb + lane);
        float4 c1 = __ldcg((const float4*)g_comb + 32 + lane);
        float gr = warp_sum(dot4(wi[0][0], c0) + dot4(wi[0][1], c1)) + bir;
        float gz = warp_sum(dot4(wi[1][0], c0) + dot4(wi[1][1], c1)) + biz;
        float gn = warp_sum(dot4(wi[2][0], c0) + dot4(wi[2][1], c1)) + bin;
        float r = 1.f / (1.f + expf(-(gr + ghr)));
        float z = 1.f / (1.f + expf(-(gz + ghz)));
        float n = tanhf(gn + r * ghn);
        float h = (1.f - z) * n + z * h0o;
        if (lane == 0) { __stcg(g_hnew + gw, h); out[29 + gw] = h; }
    }

    // prefetch P5 (CTA0 only)
    float4 wo[4][2]; float bo[4];
    if (blockIdx.x == 0) {
#pragma unroll
        for (int r = 0; r < 4; r++) {
            int o = wrp * 4 + r;
            if (o < 29) {
                const float* w = w_out + o * 256;
                wo[r][0] = __ldg((const float4*)w + lane);
                wo[r][1] = __ldg((const float4*)w + 32 + lane);
                bo[r] = __ldg(b_out + o);
            }
        }
    }
    gsync(gen0 + 4, blockIdx.x == 0);                               // ---- gb4
    if (blockIdx.x != 0) return;

    // ---- P5 (CTA0): output logits + log_softmax -----------------------------
    __shared__ float sL[32];
    {
        float4 h0x = __ldcg((const float4*)g_hnew + lane);
        float4 h1x = __ldcg((const float4*)g_hnew + 32 + lane);
#pragma unroll
        for (int r = 0; r < 4; r++) {
            int o = wrp * 4 + r;
            if (o < 29) {
                float s = warp_sum(dot4(wo[r][0], h0x) + dot4(wo[r][1], h1x)) + bo[r];
                if (lane == 0) sL[o] = s;
            }
        }
    }
    __syncthreads();
    if (wrp == 0) {
        float v = (lane < 29) ? sL[lane] : -1e30f;
        float m = warp_max(v);
        float e = (lane < 29) ? expf(v - m) : 0.f;
        float sum = warp_sum(e);
        float ls = logf(sum);
        if (lane < 29) out[lane] = v - m - ls;
    }
}

// ---------------- launch --------------------------------------------------------
extern "C" void kernel_launch(void* const* d_in, const int* in_sizes, int n_in,
                              void* d_out, int out_size) {
    (void)in_sizes; (void)n_in; (void)out_size;
    attn_decoder_fused<<<NB, NT>>>(
        (const int*)d_in[0],  (const float*)d_in[1], (const float*)d_in[2],
        (const int*)d_in[3],  (const int*)d_in[4],   (const float*)d_in[5],
        (const float*)d_in[6],(const float*)d_in[7], (const float*)d_in[8],
        (const float*)d_in[9],(const float*)d_in[10],(const float*)d_in[11],
        (const float*)d_in[12],(const float*)d_in[13],(const float*)d_in[14],
        (const float*)d_in[15],(const float*)d_in[16],(const float*)d_in[17],
        (float*)d_out);
}

// round 4
// speedup vs baseline: 1.0019x; 1.0019x over previous
#include <cuda_runtime.h>
#include <math.h>

#define NB 8
#define NT 1024
#define NWARP 32   // warps per CTA; 8*32 = 256 global warps

// ---------------- scratch (device globals; L2-resident) ------------------------
__device__ __align__(16) float g_h0[256];
__device__ __align__(16) float g_gh[768];
__device__ __align__(16) float g_comb[256];
__device__ __align__(16) float g_hnew[256];

// ---------------- helpers ------------------------------------------------------
__device__ __forceinline__ float warp_sum(float v) {
#pragma unroll
    for (int o = 16; o; o >>= 1) v += __shfl_xor_sync(0xffffffffu, v, o);
    return v;
}
__device__ __forceinline__ float warp_max(float v) {
#pragma unroll
    for (int o = 16; o; o >>= 1) v = fmaxf(v, __shfl_xor_sync(0xffffffffu, v, o));
    return v;
}
__device__ __forceinline__ float dot4(float4 a, float4 b) {
    return a.x * b.x + a.y * b.y + a.z * b.z + a.w * b.w;
}
// HW cluster barrier: includes release/acquire at cluster scope (orders our
// __stcg stores for peer CTAs' __ldcg loads). Fully graph-replay safe.
__device__ __forceinline__ void csync() {
    asm volatile("barrier.cluster.arrive.aligned;" ::: "memory");
    asm volatile("barrier.cluster.wait.aligned;" ::: "memory");
}

// ---------------- fused decoder step -------------------------------------------
__global__ void __launch_bounds__(NT, 1) __cluster_dims__(NB, 1, 1)
attn_decoder_fused(const int* __restrict__ inp,
                   const float* __restrict__ hidden,   // [256]
                   const float* __restrict__ enc,      // [20,256]
                   const int* __restrict__ cond,       // [2]
                   const int* __restrict__ is_head,    // [1]
                   const float* __restrict__ emb,      // [29,256]
                   const float* __restrict__ w_l2d,    // [256,264]
                   const float* __restrict__ b_l2d,
                   const float* __restrict__ w_attn,   // [20,512]
                   const float* __restrict__ b_attn,
                   const float* __restrict__ w_comb,   // [256,512]
                   const float* __restrict__ b_comb,
                   const float* __restrict__ w_ih,     // [768,256]
                   const float* __restrict__ w_hh,     // [768,256]
                   const float* __restrict__ b_ih,
                   const float* __restrict__ b_hh,
                   const float* __restrict__ w_out,    // [29,256]
                   const float* __restrict__ b_out,
                   float* __restrict__ out)            // [305]
{
    __shared__ float sL[32];

    const int tid  = threadIdx.x;
    const int lane = tid & 31;
    const int wrp  = tid >> 5;                       // 0..31
    const int gw   = blockIdx.x * NWARP + wrp;       // 0..255

    const int head = __ldg(is_head);
    const float* erow = emb + __ldg(inp) * 256;

    // embedded slices for this lane
    float4 e0 = __ldg((const float4*)erow + lane);
    float4 e1 = __ldg((const float4*)erow + 32 + lane);

    // ---- P1: h0 row gw (head path) + emb-half partials ----------------------
    float h0v = 0.f;                                  // h0[gw], all lanes
    if (head) {
        const float* wr = w_l2d + gw * 264;
        float4 w0 = __ldg((const float4*)wr + lane);
        float4 w1 = __ldg((const float4*)(wr + 128) + lane);
        float4 x0 = __ldg((const float4*)hidden + lane);
        float4 x1 = __ldg((const float4*)hidden + 32 + lane);
        float s = dot4(w0, x0) + dot4(w1, x1);
        int c0 = __ldg(cond), c1 = __ldg(cond + 1);
        if (lane < 8) {
            float xv = (lane == c0 || lane == 4 + c1) ? 1.f : 0.f;
            s += wr[256 + lane] * xv;
        }
        h0v = warp_sum(s) + __ldg(b_l2d + gw);
        if (lane == 0) __stcg(g_h0 + gw, h0v);
    }
    const float* wc = w_comb + gw * 512;
    float ce_p = dot4(__ldg((const float4*)wc + lane), e0) +
                 dot4(__ldg((const float4*)wc + 32 + lane), e1);   // comb emb-half, per-lane
    float ae_p = 0.f;                                              // attn emb-half (row=wrp, per-CTA redundant)
    if (wrp < 20) {
        const float* wa = w_attn + wrp * 512;
        ae_p = dot4(__ldg((const float4*)wa + lane), e0) +
               dot4(__ldg((const float4*)wa + 32 + lane), e1);
    }
    csync();                                                       // ---- cs1 (h0 ready)

    // ---- P2: gh rows (3/warp, global) + attn logits (per-CTA) + softmax +
    //          attn_applied + comb row gw ------------------------------------
    float4 x0, x1;
    if (head) {
        x0 = __ldcg((const float4*)g_h0 + lane);
        x1 = __ldcg((const float4*)g_h0 + 32 + lane);
    } else {
        x0 = __ldg((const float4*)hidden + lane);
        x1 = __ldg((const float4*)hidden + 32 + lane);
    }
#pragma unroll
    for (int r = 0; r < 3; r++) {
        const int o = gw * 3 + r;
        const float* w = w_hh + o * 256;
        float s = warp_sum(dot4(__ldg((const float4*)w + lane), x0) +
                           dot4(__ldg((const float4*)w + 32 + lane), x1));
        if (lane == 0) __stcg(g_gh + o, s + __ldg(b_hh + o));
    }
    if (wrp < 20) {
        const float* wa = w_attn + wrp * 512 + 256;
        float s = warp_sum(ae_p + dot4(__ldg((const float4*)wa + lane), x0) +
                                  dot4(__ldg((const float4*)wa + 32 + lane), x1));
        if (lane == 0) sL[wrp] = s + __ldg(b_attn + wrp);
    }
    __syncthreads();                                               // CTA-local: logits ready
    {
        float v = (lane < 20) ? sL[lane] : -1e30f;
        float m = warp_max(v);
        float ex = (lane < 20) ? expf(v - m) : 0.f;
        float sum = warp_sum(ex);
        float w = ex / sum;
        if (gw == 0 && lane < 20) out[285 + lane] = w;
        float4 a0 = {0.f, 0.f, 0.f, 0.f}, a1 = {0.f, 0.f, 0.f, 0.f};
#pragma unroll
        for (int l = 0; l < 20; l++) {
            float wl = __shfl_sync(0xffffffffu, w, l);
            float4 q0 = __ldg((const float4*)(enc + l * 256) + lane);
            float4 q1 = __ldg((const float4*)(enc + l * 256) + 32 + lane);
            a0.x += wl * q0.x; a0.y += wl * q0.y; a0.z += wl * q0.z; a0.w += wl * q0.w;
            a1.x += wl * q1.x; a1.y += wl * q1.y; a1.z += wl * q1.z; a1.w += wl * q1.w;
        }
        float sc = warp_sum(ce_p +
                            dot4(__ldg((const float4*)(wc + 256) + lane), a0) +
                            dot4(__ldg((const float4*)(wc + 256) + 32 + lane), a1));
        if (lane == 0) __stcg(g_comb + gw, fmaxf(sc + __ldg(b_comb + gw), 0.f));
    }
    csync();                                                       // ---- cs2 (gh + comb ready)

    // ---- P3: gi rows + fused GRU for element gw -----------------------------
    {
        float4 c0 = __ldcg((const float4*)g_comb + lane);
        float4 c1 = __ldcg((const float4*)g_comb + 32 + lane);
        const float* wr0 = w_ih + gw * 256;
        const float* wr1 = w_ih + (256 + gw) * 256;
        const float* wr2 = w_ih + (512 + gw) * 256;
        float gr = warp_sum(dot4(__ldg((const float4*)wr0 + lane), c0) +
                            dot4(__ldg((const float4*)wr0 + 32 + lane), c1)) + __ldg(b_ih + gw);
        float gz = warp_sum(dot4(__ldg((const float4*)wr1 + lane), c0) +
                            dot4(__ldg((const float4*)wr1 + 32 + lane), c1)) + __ldg(b_ih + 256 + gw);
        float gn = warp_sum(dot4(__ldg((const float4*)wr2 + lane), c0) +
                            dot4(__ldg((const float4*)wr2 + 32 + lane), c1)) + __ldg(b_ih + 512 + gw);
        float ghr = __ldcg(g_gh + gw);
        float ghz = __ldcg(g_gh + 256 + gw);
        float ghn = __ldcg(g_gh + 512 + gw);
        float h0o = head ? h0v : __ldg(hidden + gw);
        float r = 1.f / (1.f + expf(-(gr + ghr)));
        float z = 1.f / (1.f + expf(-(gz + ghz)));
        float n = tanhf(gn + r * ghn);
        float h = (1.f - z) * n + z * h0o;
        if (lane == 0) { __stcg(g_hnew + gw, h); out[29 + gw] = h; }
    }
    csync();                                                       // ---- cs3 (h_new ready)
    if (blockIdx.x != 0) return;

    // ---- P4 (CTA0): output logits (1 row/warp) + log_softmax ----------------
    if (wrp < 29) {
        float4 h0x = __ldcg((const float4*)g_hnew + lane);
        float4 h1x = __ldcg((const float4*)g_hnew + 32 + lane);
        const float* w = w_out + wrp * 256;
        float s = warp_sum(dot4(__ldg((const float4*)w + lane), h0x) +
                           dot4(__ldg((const float4*)w + 32 + lane), h1x));
        if (lane == 0) sL[wrp] = s + __ldg(b_out + wrp);
    }
    __syncthreads();
    if (wrp == 0) {
        float v = (lane < 29) ? sL[lane] : -1e30f;
        float m = warp_max(v);
        float e = (lane < 29) ? expf(v - m) : 0.f;
        float sum = warp_sum(e);
        float ls = logf(sum);
        if (lane < 29) out[lane] = v - m - ls;
    }
}

// ---------------- launch --------------------------------------------------------
extern "C" void kernel_launch(void* const* d_in, const int* in_sizes, int n_in,
                              void* d_out, int out_size) {
    (void)in_sizes; (void)n_in; (void)out_size;
    attn_decoder_fused<<<NB, NT>>>(
        (const int*)d_in[0],  (const float*)d_in[1], (const float*)d_in[2],
        (const int*)d_in[3],  (const int*)d_in[4],   (const float*)d_in[5],
        (const float*)d_in[6],(const float*)d_in[7], (const float*)d_in[8],
        (const float*)d_in[9],(const float*)d_in[10],(const float*)d_in[11],
        (const float*)d_in[12],(const float*)d_in[13],(const float*)d_in[14],
        (const float*)d_in[15],(const float*)d_in[16],(const float*)d_in[17],
        (float*)d_out);
}

// round 6
// speedup vs baseline: 1.1404x; 1.1382x over previous
#include <cuda_runtime.h>
#include <cstdint>
#include <math.h>

#define NB 8
#define NT 512
#define NWARP 16   // warps per CTA; 8*16 = 128 global warps, 2 elements each

// ---------------- helpers ------------------------------------------------------
__device__ __forceinline__ float warp_sum(float v) {
#pragma unroll
    for (int o = 16; o; o >>= 1) v += __shfl_xor_sync(0xffffffffu, v, o);
    return v;
}
__device__ __forceinline__ float warp_max(float v) {
#pragma unroll
    for (int o = 16; o; o >>= 1) v = fmaxf(v, __shfl_xor_sync(0xffffffffu, v, o));
    return v;
}
__device__ __forceinline__ float dot4(float4 a, float4 b) {
    return a.x * b.x + a.y * b.y + a.z * b.z + a.w * b.w;
}
__device__ __forceinline__ uint32_t smem_u32(const void* p) {
    uint32_t a;
    asm("{.reg .u64 t; cvta.to.shared.u64 t,%1; cvt.u32.u64 %0,t;}" : "=r"(a) : "l"(p));
    return a;
}
// store 4B to the same smem offset in CTA `rank` of the cluster
__device__ __forceinline__ void st_cluster(uint32_t laddr, int rank, float v) {
    uint32_t ra;
    asm("mapa.shared::cluster.u32 %0,%1,%2;" : "=r"(ra) : "r"(laddr), "r"(rank));
    asm volatile("st.shared::cluster.f32 [%0],%1;" :: "r"(ra), "f"(v) : "memory");
}
// HW cluster barrier (release/acquire at cluster scope covers DSMEM stores)
__device__ __forceinline__ void csync() {
    asm volatile("barrier.cluster.arrive.aligned;" ::: "memory");
    asm volatile("barrier.cluster.wait.aligned;" ::: "memory");
}

// ---------------- fused decoder step -------------------------------------------
__global__ void __launch_bounds__(NT, 1) __cluster_dims__(NB, 1, 1)
attn_decoder_fused(const int* __restrict__ inp,
                   const float* __restrict__ hidden,   // [256]
                   const float* __restrict__ enc,      // [20,256]
                   const int* __restrict__ cond,       // [2]
                   const int* __restrict__ is_head,    // [1]
                   const float* __restrict__ emb,      // [29,256]
                   const float* __restrict__ w_l2d,    // [256,264]
                   const float* __restrict__ b_l2d,
                   const float* __restrict__ w_attn,   // [20,512]
                   const float* __restrict__ b_attn,
                   const float* __restrict__ w_comb,   // [256,512]
                   const float* __restrict__ b_comb,
                   const float* __restrict__ w_ih,     // [768,256]
                   const float* __restrict__ w_hh,     // [768,256]
                   const float* __restrict__ b_ih,
                   const float* __restrict__ b_hh,
                   const float* __restrict__ w_out,    // [29,256]
                   const float* __restrict__ b_out,
                   float* __restrict__ out)            // [305]
{
    __shared__ __align__(16) float sHid[256];
    __shared__ __align__(16) float sH0[256];
    __shared__ __align__(16) float sEnc[20 * 256];
    __shared__ __align__(16) float sComb[256];
    __shared__ __align__(16) float sHnew[256];
    __shared__ float sL[32];

    const int tid  = threadIdx.x;
    const int lane = tid & 31;
    const int wrp  = tid >> 5;                        // 0..15
    const int gw   = blockIdx.x * NWARP + wrp;        // 0..127
    const int e0i  = gw, e1i = gw + 128;              // elements owned by this warp

    const int head = __ldg(is_head);
    const float* erow = emb + __ldg(inp) * 256;

    // ---- stage hidden + enc into smem (overlaps with P1 latency) ------------
    if (tid < 64) ((float4*)sHid)[tid] = __ldg((const float4*)hidden + tid);
    for (int i = tid; i < 20 * 64; i += NT)
        ((float4*)sEnc)[i] = __ldg((const float4*)enc + i);

    // embedded slices for this lane
    float4 e0 = __ldg((const float4*)erow + lane);
    float4 e1 = __ldg((const float4*)erow + 32 + lane);
    __syncthreads();                                   // sHid ready

    // ---- P1: h0 rows e0i,e1i (head) + emb-half partials ---------------------
    float4 hx0 = *((const float4*)sHid + lane);
    float4 hx1 = *((const float4*)sHid + 32 + lane);
    float h00 = 0.f, h01 = 0.f;
    if (head) {
        int c0 = __ldg(cond), c1 = __ldg(cond + 1);
#pragma unroll
        for (int e = 0; e < 2; e++) {
            const int o = e ? e1i : e0i;
            const float* wr = w_l2d + o * 264;
            float s = dot4(__ldg((const float4*)wr + lane), hx0) +
                      dot4(__ldg((const float4*)(wr + 128) + lane), hx1);
            if (lane < 8) {
                float xv = (lane == c0 || lane == 4 + c1) ? 1.f : 0.f;
                s += wr[256 + lane] * xv;
            }
            s = warp_sum(s) + __ldg(b_l2d + o);
            if (e) h01 = s; else h00 = s;
        }
        // replicate to all 8 CTAs' sH0 (lanes 0-7: e0i, lanes 8-15: e1i)
        if (lane < 8)       st_cluster(smem_u32(&sH0[e0i]), lane, h00);
        else if (lane < 16) st_cluster(smem_u32(&sH0[e1i]), lane - 8, h01);
    }
    // comb emb-half partials (per-lane, finished in P2)
    const float* wc0 = w_comb + e0i * 512;
    const float* wc1 = w_comb + e1i * 512;
    float ce0 = dot4(__ldg((const float4*)wc0 + lane), e0) +
                dot4(__ldg((const float4*)wc0 + 32 + lane), e1);
    float ce1 = dot4(__ldg((const float4*)wc1 + lane), e0) +
                dot4(__ldg((const float4*)wc1 + 32 + lane), e1);
    // attn rows handled per-CTA: r1=wrp, r2=16+wrp (wrp<4)
    float ae1 = 0.f, ae2 = 0.f;
    {
        const float* wa = w_attn + wrp * 512;
        ae1 = dot4(__ldg((const float4*)wa + lane), e0) +
              dot4(__ldg((const float4*)wa + 32 + lane), e1);
        if (wrp < 4) {
            const float* wb = w_attn + (16 + wrp) * 512;
            ae2 = dot4(__ldg((const float4*)wb + lane), e0) +
                  dot4(__ldg((const float4*)wb + 32 + lane), e1);
        }
    }
    // ---- prefetch P2 weights into registers (overlaps barrier) --------------
    float4 wh[6][2]; float bh[6];
#pragma unroll
    for (int r = 0; r < 6; r++) {
        const int o = (r % 3) * 256 + (r < 3 ? e0i : e1i);
        const float* w = w_hh + o * 256;
        wh[r][0] = __ldg((const float4*)w + lane);
        wh[r][1] = __ldg((const float4*)w + 32 + lane);
        bh[r] = __ldg(b_hh + o);
    }
    float4 wa1_0, wa1_1, wa2_0, wa2_1;
    {
        const float* wa = w_attn + wrp * 512 + 256;
        wa1_0 = __ldg((const float4*)wa + lane);
        wa1_1 = __ldg((const float4*)wa + 32 + lane);
        if (wrp < 4) {
            const float* wb = w_attn + (16 + wrp) * 512 + 256;
            wa2_0 = __ldg((const float4*)wb + lane);
            wa2_1 = __ldg((const float4*)wb + 32 + lane);
        }
    }
    float4 wch0_0 = __ldg((const float4*)(wc0 + 256) + lane);
    float4 wch0_1 = __ldg((const float4*)(wc0 + 256) + 32 + lane);
    float4 wch1_0 = __ldg((const float4*)(wc1 + 256) + lane);
    float4 wch1_1 = __ldg((const float4*)(wc1 + 256) + 32 + lane);
    csync();                                                       // ---- cs1

    // ---- P2: gh (registers!) + attn logits + softmax + attn_applied + comb --
    float4 x0, x1;
    if (head) { x0 = *((const float4*)sH0 + lane); x1 = *((const float4*)sH0 + 32 + lane); }
    else      { x0 = hx0; x1 = hx1; }
    float ghv[6];
#pragma unroll
    for (int r = 0; r < 6; r++)
        ghv[r] = warp_sum(dot4(wh[r][0], x0) + dot4(wh[r][1], x1)) + bh[r];
    {
        float s = warp_sum(ae1 + dot4(wa1_0, x0) + dot4(wa1_1, x1));
        if (lane == 0) sL[wrp] = s + __ldg(b_attn + wrp);
        if (wrp < 4) {
            float s2 = warp_sum(ae2 + dot4(wa2_0, x0) + dot4(wa2_1, x1));
            if (lane == 0) sL[16 + wrp] = s2 + __ldg(b_attn + 16 + wrp);
        }
    }
    __syncthreads();                                   // logits ready (CTA-local)
    {
        float v = (lane < 20) ? sL[lane] : -1e30f;
        float m = warp_max(v);
        float ex = (lane < 20) ? expf(v - m) : 0.f;
        float sum = warp_sum(ex);
        float w = ex / sum;
        if (gw == 0 && lane < 20) out[285 + lane] = w;
        float4 a0 = {0.f,0.f,0.f,0.f}, a1 = {0.f,0.f,0.f,0.f};
#pragma unroll
        for (int l = 0; l < 20; l++) {
            float wl = __shfl_sync(0xffffffffu, w, l);
            float4 q0 = *((const float4*)(sEnc + l * 256) + lane);
            float4 q1 = *((const float4*)(sEnc + l * 256) + 32 + lane);
            a0.x += wl*q0.x; a0.y += wl*q0.y; a0.z += wl*q0.z; a0.w += wl*q0.w;
            a1.x += wl*q1.x; a1.y += wl*q1.y; a1.z += wl*q1.z; a1.w += wl*q1.w;
        }
        float sc0 = warp_sum(ce0 + dot4(wch0_0, a0) + dot4(wch0_1, a1));
        float sc1 = warp_sum(ce1 + dot4(wch1_0, a0) + dot4(wch1_1, a1));
        sc0 = fmaxf(sc0 + __ldg(b_comb + e0i), 0.f);
        sc1 = fmaxf(sc1 + __ldg(b_comb + e1i), 0.f);
        if (lane < 8)       st_cluster(smem_u32(&sComb[e0i]), lane, sc0);
        else if (lane < 16) st_cluster(smem_u32(&sComb[e1i]), lane - 8, sc1);
    }
    // ---- prefetch P3 weights (overlaps barrier) -----------------------------
    float4 wi[6][2]; float bi[6];
#pragma unroll
    for (int r = 0; r < 6; r++) {
        const int o = (r % 3) * 256 + (r < 3 ? e0i : e1i);
        const float* w = w_ih + o * 256;
        wi[r][0] = __ldg((const float4*)w + lane);
        wi[r][1] = __ldg((const float4*)w + 32 + lane);
        bi[r] = __ldg(b_ih + o);
    }
    csync();                                                       // ---- cs2

    // ---- P3: gi + fused GRU (gh already in registers) -----------------------
    {
        float4 c0 = *((const float4*)sComb + lane);
        float4 c1 = *((const float4*)sComb + 32 + lane);
        float gi[6];
#pragma unroll
        for (int r = 0; r < 6; r++)
            gi[r] = warp_sum(dot4(wi[r][0], c0) + dot4(wi[r][1], c1)) + bi[r];
#pragma unroll
        for (int e = 0; e < 2; e++) {
            const int o = e ? e1i : e0i;
            float h0o = head ? (e ? h01 : h00) : sHid[o];
            float r = 1.f / (1.f + expf(-(gi[e*3+0] + ghv[e*3+0])));
            float z = 1.f / (1.f + expf(-(gi[e*3+1] + ghv[e*3+1])));
            float n = tanhf(gi[e*3+2] + r * ghv[e*3+2]);
            float h = (1.f - z) * n + z * h0o;
            if (lane == 0) {
                st_cluster(smem_u32(&sHnew[o]), 0, h);   // to CTA0 only
                out[29 + o] = h;
            }
        }
    }
    // ---- prefetch P4 weights (CTA0) -----------------------------------------
    float4 wo[2][2]; float bo[2];
    if (blockIdx.x == 0) {
#pragma unroll
        for (int r = 0; r < 2; r++) {
            const int o = wrp * 2 + r;
            if (o < 29) {
                const float* w = w_out + o * 256;
                wo[r][0] = __ldg((const float4*)w + lane);
                wo[r][1] = __ldg((const float4*)w + 32 + lane);
                bo[r] = __ldg(b_out + o);
            }
        }
    }
    csync();                                                       // ---- cs3
    if (blockIdx.x != 0) return;

    // ---- P4 (CTA0): output logits + log_softmax -----------------------------
    {
        float4 h0x = *((const float4*)sHnew + lane);
        float4 h1x = *((const float4*)sHnew + 32 + lane);
#pragma unroll
        for (int r = 0; r < 2; r++) {
            const int o = wrp * 2 + r;
            if (o < 29) {
                float s = warp_sum(dot4(wo[r][0], h0x) + dot4(wo[r][1], h1x)) + bo[r];
                if (lane == 0) sL[o] = s;
            }
        }
    }
    __syncthreads();
    if (wrp == 0) {
        float v = (lane < 29) ? sL[lane] : -1e30f;
        float m = warp_max(v);
        float e = (lane < 29) ? expf(v - m) : 0.f;
        float sum = warp_sum(e);
        float ls = logf(sum);
        if (lane < 29) out[lane] = v - m - ls;
    }
}

// ---------------- launch --------------------------------------------------------
extern "C" void kernel_launch(void* const* d_in, const int* in_sizes, int n_in,
                              void* d_out, int out_size) {
    (void)in_sizes; (void)n_in; (void)out_size;
    attn_decoder_fused<<<NB, NT>>>(
        (const int*)d_in[0],  (const float*)d_in[1], (const float*)d_in[2],
        (const int*)d_in[3],  (const int*)d_in[4],   (const float*)d_in[5],
        (const float*)d_in[6],(const float*)d_in[7], (const float*)d_in[8],
        (const float*)d_in[9],(const float*)d_in[10],(const float*)d_in[11],
        (const float*)d_in[12],(const float*)d_in[13],(const float*)d_in[14],
        (const float*)d_in[15],(const float*)d_in[16],(const float*)d_in[17],
        (float*)d_out);
}